// round 1
// baseline (speedup 1.0000x reference)
#include <cuda_runtime.h>
#include <math.h>

#define BATCH 65536
#define NQ 8

// ---------------- device scratch (no allocations allowed) ----------------
__device__ float d_W1f[128 * 16];
__device__ float d_b1f[128];
__device__ float d_W2f[64 * 128];
__device__ float d_b2f[64];
__device__ float d_W4f[32 * 8];
__device__ float d_b4f[32];
__device__ float d_qp[72 * 2];            // (cos, sin) of theta/2 for each of 3*8*3 gates
__device__ float d_angles[BATCH * NQ];    // tanh outputs (quantum input angles)
__device__ float d_qout[BATCH * NQ];      // <Z_q> expectations

// ---------------- precompute: fold BN into weights, gate params ----------------
__global__ void precompute_kernel(
    const float* W1, const float* b1, const float* g1, const float* bt1, const float* m1, const float* v1,
    const float* W2, const float* b2, const float* g2, const float* bt2, const float* m2, const float* v2,
    const float* W4, const float* b4, const float* g4, const float* bt4, const float* m4, const float* v4,
    const float* qw)
{
    int t = threadIdx.x;  // 128 threads
    if (t < 128) {
        float a = g1[t] * rsqrtf(v1[t] + 1e-5f);
        for (int k = 0; k < 16; k++) d_W1f[t * 16 + k] = W1[t * 16 + k] * a;
        d_b1f[t] = (b1[t] - m1[t]) * a + bt1[t];
    }
    if (t < 64) {
        float a = g2[t] * rsqrtf(v2[t] + 1e-5f);
        for (int k = 0; k < 128; k++) d_W2f[t * 128 + k] = W2[t * 128 + k] * a;
        d_b2f[t] = (b2[t] - m2[t]) * a + bt2[t];
    }
    if (t < 32) {
        float a = g4[t] * rsqrtf(v4[t] + 1e-5f);
        for (int k = 0; k < 8; k++) d_W4f[t * 8 + k] = W4[t * 8 + k] * a;
        d_b4f[t] = (b4[t] - m4[t]) * a + bt4[t];
    }
    if (t < 72) {
        float th = 0.5f * qw[t];
        d_qp[2 * t + 0] = cosf(th);
        d_qp[2 * t + 1] = sinf(th);
    }
}

// ---------------- front MLP: x[B,16] -> angles[B,8] ----------------
#define FRONT_BLOCKS 1024
#define FRONT_ROWS   (BATCH / FRONT_BLOCKS)   // 64

__global__ void __launch_bounds__(128) front_kernel(const float* __restrict__ x,
                                                    const float* __restrict__ W3,
                                                    const float* __restrict__ b3)
{
    __shared__ float W1T[16 * 128];   // [k][t]
    __shared__ float W2T[128 * 64];   // [k][o]
    __shared__ float W3T[64 * 8];     // [k][o]
    __shared__ float b1s[128], b2s[64], b3s[8];
    __shared__ float xs[2][16];
    __shared__ float h1s[2][128];
    __shared__ float h2s[2][64];

    int t = threadIdx.x;  // 128
    for (int i = t; i < 128 * 16; i += 128) { int r = i / 16,  k = i % 16;  W1T[k * 128 + r] = d_W1f[i]; }
    for (int i = t; i < 64 * 128; i += 128) { int r = i / 128, k = i % 128; W2T[k * 64 + r]  = d_W2f[i]; }
    for (int i = t; i < 8 * 64;   i += 128) { int r = i / 64,  k = i % 64;  W3T[k * 8 + r]   = W3[i]; }
    if (t < 128) b1s[t] = d_b1f[t];
    if (t < 64)  b2s[t] = d_b2f[t];
    if (t < 8)   b3s[t] = b3[t];
    __syncthreads();

    int base = blockIdx.x * FRONT_ROWS;
    for (int it = 0; it < FRONT_ROWS / 2; it++) {
        int row0 = base + it * 2;
        if (t < 32) xs[t >> 4][t & 15] = x[(row0 + (t >> 4)) * 16 + (t & 15)];
        __syncthreads();
        {
            float a0 = b1s[t], a1 = a0;
            #pragma unroll
            for (int k = 0; k < 16; k++) {
                float w = W1T[k * 128 + t];
                a0 += w * xs[0][k];
                a1 += w * xs[1][k];
            }
            h1s[0][t] = fmaxf(a0, 0.f);
            h1s[1][t] = fmaxf(a1, 0.f);
        }
        __syncthreads();
        {
            int rr = t >> 6, o = t & 63;
            float acc = b2s[o];
            #pragma unroll
            for (int k = 0; k < 128; k++) acc += W2T[k * 64 + o] * h1s[rr][k];
            h2s[rr][o] = fmaxf(acc, 0.f);
        }
        __syncthreads();
        if (t < 16) {
            int rr = t >> 3, o = t & 7;
            float acc = b3s[o];
            #pragma unroll
            for (int k = 0; k < 64; k++) acc += W3T[k * 8 + o] * h2s[rr][k];
            d_angles[(row0 + rr) * 8 + o] = tanhf(acc);
        }
        __syncthreads();
    }
}

// ---------------- quantum: warp-per-element statevector sim ----------------
// amp index i[7:0]: bits 7..3 = lane bits 4..0 ; bits 2..0 = local register index.
// qubit q acts on amp bit B = 7-q.
// Reference applies U^T (einsum 'st,bpsq->bptq'), so effective RY = [[c,s],[-s,c]];
// RX and RZ are transpose-invariant.

#define FULLM 0xffffffffu

template <int B>
__device__ __forceinline__ void g_rx(float2 st[8], float c, float sv, int lane)
{
    if (B >= 3) {
        float pr[8], pi[8];
        #pragma unroll
        for (int r = 0; r < 8; r++) {
            pr[r] = __shfl_xor_sync(FULLM, st[r].x, 1 << (B - 3));
            pi[r] = __shfl_xor_sync(FULLM, st[r].y, 1 << (B - 3));
        }
        #pragma unroll
        for (int r = 0; r < 8; r++) {
            float nr = c * st[r].x + sv * pi[r];
            float ni = c * st[r].y - sv * pr[r];
            st[r].x = nr; st[r].y = ni;
        }
    } else {
        #pragma unroll
        for (int r0 = 0; r0 < 8; r0++) {
            if ((r0 >> B) & 1) continue;
            int r1 = r0 | (1 << B);
            float a0r = st[r0].x, a0i = st[r0].y;
            float a1r = st[r1].x, a1i = st[r1].y;
            st[r0].x = c * a0r + sv * a1i;  st[r0].y = c * a0i - sv * a1r;
            st[r1].x = c * a1r + sv * a0i;  st[r1].y = c * a1i - sv * a0r;
        }
    }
}

template <int B>
__device__ __forceinline__ void g_ry(float2 st[8], float c, float sv, int lane)
{
    if (B >= 3) {
        int m = (lane >> (B - 3)) & 1;
        float sg = m ? -sv : sv;    // new = c*a + sg*partner
        #pragma unroll
        for (int r = 0; r < 8; r++) {
            float pr = __shfl_xor_sync(FULLM, st[r].x, 1 << (B - 3));
            float pi = __shfl_xor_sync(FULLM, st[r].y, 1 << (B - 3));
            st[r].x = c * st[r].x + sg * pr;
            st[r].y = c * st[r].y + sg * pi;
        }
    } else {
        #pragma unroll
        for (int r0 = 0; r0 < 8; r0++) {
            if ((r0 >> B) & 1) continue;
            int r1 = r0 | (1 << B);
            float a0r = st[r0].x, a0i = st[r0].y;
            float a1r = st[r1].x, a1i = st[r1].y;
            st[r0].x = c * a0r + sv * a1r;  st[r0].y = c * a0i + sv * a1i;
            st[r1].x = c * a1r - sv * a0r;  st[r1].y = c * a1i - sv * a0i;
        }
    }
}

template <int B>
__device__ __forceinline__ void g_rz(float2 st[8], float c, float sv, int lane)
{
    #pragma unroll
    for (int r = 0; r < 8; r++) {
        int m = (B >= 3) ? ((lane >> (B - 3)) & 1) : ((r >> B) & 1);
        float sg = m ? -sv : sv;
        float ar = st[r].x, ai = st[r].y;
        st[r].x = c * ar + sg * ai;
        st[r].y = c * ai - sg * ar;
    }
}

template <int CB, int TB>
__device__ __forceinline__ void g_cnot(float2 st[8], int lane)
{
    if (CB >= 3 && TB >= 3) {
        bool ctrl = (lane >> (CB - 3)) & 1;
        #pragma unroll
        for (int r = 0; r < 8; r++) {
            float pr = __shfl_xor_sync(FULLM, st[r].x, 1 << (TB - 3));
            float pi = __shfl_xor_sync(FULLM, st[r].y, 1 << (TB - 3));
            if (ctrl) { st[r].x = pr; st[r].y = pi; }
        }
    } else if (CB >= 3) {   // control in lane bits, target in local bits
        bool ctrl = (lane >> (CB - 3)) & 1;
        #pragma unroll
        for (int r0 = 0; r0 < 8; r0++) {
            if ((r0 >> TB) & 1) continue;
            int r1 = r0 | (1 << TB);
            float2 t0 = st[r0], t1 = st[r1];
            st[r0] = ctrl ? t1 : t0;
            st[r1] = ctrl ? t0 : t1;
        }
    } else {                // both local (TB < CB < 3)
        #pragma unroll
        for (int r0 = 0; r0 < 8; r0++) {
            if (!((r0 >> CB) & 1)) continue;
            if ((r0 >> TB) & 1) continue;
            int r1 = r0 | (1 << TB);
            float2 tmp = st[r0]; st[r0] = st[r1]; st[r1] = tmp;
        }
    }
}

template <int Q>
__device__ __forceinline__ void apply_qubit(float2 st[8], const float* __restrict__ p, int lane)
{
    constexpr int B = 7 - Q;
    float cx = p[Q * 6 + 0], sx = p[Q * 6 + 1];
    float cy = p[Q * 6 + 2], sy = p[Q * 6 + 3];
    float cz = p[Q * 6 + 4], sz = p[Q * 6 + 5];
    g_rx<B>(st, cx, sx, lane);
    g_ry<B>(st, cy, sy, lane);
    g_rz<B>(st, cz, sz, lane);
}

__global__ void __launch_bounds__(256) quantum_kernel()
{
    int warp_global = (blockIdx.x * blockDim.x + threadIdx.x) >> 5;
    int lane = threadIdx.x & 31;
    int e = warp_global;

    // ---- initial product state from RY(angles) on |0>: amp factor (bit? -s : c) ----
    float lamp = 1.f;
    #pragma unroll
    for (int q = 0; q < 5; q++) {
        float th = d_angles[e * 8 + q] * 0.5f;
        float sq, cq; __sincosf(th, &sq, &cq);
        lamp *= ((lane >> (4 - q)) & 1) ? -sq : cq;
    }
    float lc[3], ls[3];
    #pragma unroll
    for (int q = 5; q < 8; q++) {
        float th = d_angles[e * 8 + q] * 0.5f;
        __sincosf(th, &ls[q - 5], &lc[q - 5]);
    }
    float2 st[8];
    #pragma unroll
    for (int r = 0; r < 8; r++) {
        float v = lamp;
        v *= ((r >> 2) & 1) ? -ls[0] : lc[0];   // qubit 5 -> bit 2
        v *= ((r >> 1) & 1) ? -ls[1] : lc[1];   // qubit 6 -> bit 1
        v *= ( r       & 1) ? -ls[2] : lc[2];   // qubit 7 -> bit 0
        st[r].x = v; st[r].y = 0.f;
    }

    // ---- 3 variational layers ----
    for (int l = 0; l < 3; l++) {
        const float* p = d_qp + l * 48;
        apply_qubit<0>(st, p, lane);
        apply_qubit<1>(st, p, lane);
        apply_qubit<2>(st, p, lane);
        apply_qubit<3>(st, p, lane);
        apply_qubit<4>(st, p, lane);
        apply_qubit<5>(st, p, lane);
        apply_qubit<6>(st, p, lane);
        apply_qubit<7>(st, p, lane);
        // CNOT ladder: for i<j, control bit = 7-i, target bit = 7-j
        #define CN(i, j) g_cnot<7 - (i), 7 - (j)>(st, lane)
        CN(0,1); CN(0,2); CN(0,3); CN(0,4); CN(0,5); CN(0,6); CN(0,7);
        CN(1,2); CN(1,3); CN(1,4); CN(1,5); CN(1,6); CN(1,7);
        CN(2,3); CN(2,4); CN(2,5); CN(2,6); CN(2,7);
        CN(3,4); CN(3,5); CN(3,6); CN(3,7);
        CN(4,5); CN(4,6); CN(4,7);
        CN(5,6); CN(5,7);
        CN(6,7);
        #undef CN
    }

    // ---- <Z_q> = sum_i (+-1)^bit * |amp_i|^2 ----
    float ps = 0.f, z5 = 0.f, z6 = 0.f, z7 = 0.f;
    #pragma unroll
    for (int r = 0; r < 8; r++) {
        float p = st[r].x * st[r].x + st[r].y * st[r].y;
        ps += p;
        z5 += ((r >> 2) & 1) ? -p : p;
        z6 += ((r >> 1) & 1) ? -p : p;
        z7 += ( r       & 1) ? -p : p;
    }
    float acc[8];
    #pragma unroll
    for (int q = 0; q < 5; q++) acc[q] = ((lane >> (4 - q)) & 1) ? -ps : ps;
    acc[5] = z5; acc[6] = z6; acc[7] = z7;
    #pragma unroll
    for (int off = 16; off; off >>= 1) {
        #pragma unroll
        for (int q = 0; q < 8; q++) acc[q] += __shfl_xor_sync(FULLM, acc[q], off);
    }
    if (lane == 0) {
        #pragma unroll
        for (int q = 0; q < 8; q++) d_qout[e * 8 + q] = acc[q];
    }
}

// ---------------- tail MLP: qout[B,8] -> out[B,1] ----------------
__global__ void __launch_bounds__(256) tail_kernel(const float* __restrict__ W5, const float* __restrict__ b5,
                                                   const float* __restrict__ W6, const float* __restrict__ b6,
                                                   float* __restrict__ out)
{
    __shared__ float w4s[32 * 8], b4s[32], w5s[16 * 32], b5s[16], w6s[16], b6s;
    int t = threadIdx.x;  // 256
    w4s[t] = d_W4f[t];                             // exactly 256 elements
    if (t < 32) b4s[t] = d_b4f[t];
    for (int i = t; i < 16 * 32; i += 256) w5s[i] = W5[i];
    if (t < 16) { b5s[t] = b5[t]; w6s[t] = W6[t]; }
    if (t == 0) b6s = b6[0];
    __syncthreads();

    int e = blockIdx.x * 256 + t;
    float4 qa = *(const float4*)&d_qout[e * 8];
    float4 qb = *(const float4*)&d_qout[e * 8 + 4];
    float q[8] = {qa.x, qa.y, qa.z, qa.w, qb.x, qb.y, qb.z, qb.w};

    float h5[16];
    #pragma unroll
    for (int j = 0; j < 16; j++) h5[j] = b5s[j];
    #pragma unroll
    for (int o = 0; o < 32; o++) {
        float a = b4s[o];
        #pragma unroll
        for (int k = 0; k < 8; k++) a += w4s[o * 8 + k] * q[k];
        a = fmaxf(a, 0.f);
        #pragma unroll
        for (int j = 0; j < 16; j++) h5[j] += w5s[j * 32 + o] * a;
    }
    float o6 = b6s;
    #pragma unroll
    for (int j = 0; j < 16; j++) o6 += fmaxf(h5[j], 0.f) * w6s[j];
    out[e] = o6;
}

// ---------------- launch ----------------
extern "C" void kernel_launch(void* const* d_in, const int* in_sizes, int n_in,
                              void* d_out, int out_size)
{
    const float* x   = (const float*)d_in[0];
    const float* W1  = (const float*)d_in[1];
    const float* b1  = (const float*)d_in[2];
    const float* g1  = (const float*)d_in[3];
    const float* bt1 = (const float*)d_in[4];
    const float* m1  = (const float*)d_in[5];
    const float* v1  = (const float*)d_in[6];
    const float* W2  = (const float*)d_in[7];
    const float* b2  = (const float*)d_in[8];
    const float* g2  = (const float*)d_in[9];
    const float* bt2 = (const float*)d_in[10];
    const float* m2  = (const float*)d_in[11];
    const float* v2  = (const float*)d_in[12];
    const float* W3  = (const float*)d_in[13];
    const float* b3  = (const float*)d_in[14];
    const float* qw  = (const float*)d_in[15];
    const float* W4  = (const float*)d_in[16];
    const float* b4  = (const float*)d_in[17];
    const float* g4  = (const float*)d_in[18];
    const float* bt4 = (const float*)d_in[19];
    const float* m4  = (const float*)d_in[20];
    const float* v4  = (const float*)d_in[21];
    const float* W5  = (const float*)d_in[22];
    const float* b5  = (const float*)d_in[23];
    const float* W6  = (const float*)d_in[24];
    const float* b6  = (const float*)d_in[25];

    precompute_kernel<<<1, 128>>>(W1, b1, g1, bt1, m1, v1,
                                  W2, b2, g2, bt2, m2, v2,
                                  W4, b4, g4, bt4, m4, v4, qw);
    front_kernel<<<FRONT_BLOCKS, 128>>>(x, W3, b3);
    quantum_kernel<<<BATCH / 8, 256>>>();
    tail_kernel<<<BATCH / 256, 256>>>(W5, b5, W6, b6, (float*)d_out);
}

// round 5
// speedup vs baseline: 1.5953x; 1.5953x over previous
#include <cuda_runtime.h>
#include <math.h>

#define BATCH 65536
#define NQ 8
#define FULLM 0xffffffffu

typedef unsigned char u8;

// ================= compile-time GF(2) algebra for CNOT ladder =================
struct M8 { u8 c[8]; };   // c[j] = column j bitmask (bit i set => M[i][j]=1)

__host__ __device__ constexpr u8 mv(const M8& m, u8 x) {
    u8 y = 0;
    for (int j = 0; j < 8; j++) if ((x >> j) & 1) y = (u8)(y ^ m.c[j]);
    return y;
}
__host__ __device__ constexpr M8 mm(const M8& a, const M8& b) {
    M8 r{}; for (int j = 0; j < 8; j++) r.c[j] = mv(a, b.c[j]); return r;
}
__host__ __device__ constexpr M8 ident() {
    M8 m{}; for (int j = 0; j < 8; j++) m.c[j] = (u8)(1u << j); return m;
}
// lookup map of the full CNOT ladder: state_new[k] = state_old[L k]
__host__ __device__ constexpr M8 ladder() {
    M8 L = ident();
    for (int i = 0; i < 8; i++)
        for (int j = i + 1; j < 8; j++) {
            int cb = 7 - i, tb = 7 - j;           // control bit, target bit
            M8 P = ident();
            P.c[cb] = (u8)((1u << cb) | (1u << tb));  // y_t = x_t ^ x_c
            L = mm(L, P);                              // L = P1*P2*...*Pm
        }
    return L;
}
__host__ __device__ constexpr M8 minv(const M8& a) {
    u8 row[8] = {}, inv[8] = {};
    for (int i = 0; i < 8; i++) inv[i] = (u8)(1u << i);
    for (int i = 0; i < 8; i++)
        for (int j = 0; j < 8; j++)
            if ((a.c[j] >> i) & 1) row[i] = (u8)(row[i] | (1u << j));
    for (int col = 0; col < 8; col++) {
        int piv = col;
        while (!((row[piv] >> col) & 1)) piv++;
        u8 t = row[col]; row[col] = row[piv]; row[piv] = t;
        t = inv[col]; inv[col] = inv[piv]; inv[piv] = t;
        for (int i = 0; i < 8; i++)
            if (i != col && ((row[i] >> col) & 1)) { row[i] = (u8)(row[i] ^ row[col]); inv[i] = (u8)(inv[i] ^ inv[col]); }
    }
    M8 r{};
    for (int i = 0; i < 8; i++)
        for (int j = 0; j < 8; j++)
            if ((inv[i] >> j) & 1) r.c[j] = (u8)(r.c[j] | (1u << i));
    return r;
}
__host__ __device__ constexpr int par8(int x) { x ^= x >> 4; x ^= x >> 2; x ^= x >> 1; return x & 1; }

struct Masks {
    u8 v[3][8];   // pairing XOR mask   [layer][qubit]
    u8 r[3][8];   // branch parity mask [layer][qubit]
    u8 rf[8];     // final Z-parity mask per qubit
};
__host__ __device__ constexpr Masks make_masks() {
    Masks mk{};
    M8 L = ladder();
    M8 C = ident();
    for (int l = 0; l < 3; l++) {
        M8 Ci = minv(C);
        for (int q = 0; q < 8; q++) {
            int B = 7 - q;
            mk.v[l][q] = mv(C, (u8)(1u << B));        // column B of C
            u8 rr = 0;                                 // row B of C^-1
            for (int j = 0; j < 8; j++) if ((Ci.c[j] >> B) & 1) rr = (u8)(rr | (1u << j));
            mk.r[l][q] = rr;
        }
        C = mm(C, L);
    }
    M8 Cf = minv(C);
    for (int q = 0; q < 8; q++) {
        int B = 7 - q;
        u8 rr = 0;
        for (int j = 0; j < 8; j++) if ((Cf.c[j] >> B) & 1) rr = (u8)(rr | (1u << j));
        mk.rf[q] = rr;
    }
    return mk;
}
constexpr Masks MK = make_masks();

__host__ __device__ constexpr bool masks_ok() {
    constexpr Masks mk = make_masks();
    M8 L = ladder();
    M8 C = ident();
    for (int l = 0; l < 3; l++) {
        M8 Ci = minv(C);
        M8 P = mm(C, Ci);
        for (int j = 0; j < 8; j++) if (P.c[j] != (u8)(1u << j)) return false;
        for (int q = 0; q < 8; q++)
            if (par8(mk.v[l][q] & mk.r[l][q]) != 1) return false;   // branch bit must split pair
        C = mm(C, L);
    }
    return true;
}
static_assert(masks_ok(), "GF(2) mask algebra broken");

// ================= device scratch =================
__device__ float  d_W1f[128 * 16];
__device__ float  d_b1f[128];
__device__ float4 d_W2f4[64 * 32];     // BN-folded W2, natural [o][k] layout
__device__ float  d_b2f[64];
__device__ float  d_W4f[32 * 8];
__device__ float  d_b4f[32];
__device__ float4 d_qg[24];            // combined SU(2) gate per (layer,qubit): {ar, ai, br, bi}
__device__ float  d_angles[BATCH * NQ];
__device__ float  d_qout[BATCH * NQ];

// ================= precompute =================
__global__ void precompute_kernel(
    const float* W1, const float* b1, const float* g1, const float* bt1, const float* m1, const float* v1,
    const float* W2, const float* b2, const float* g2, const float* bt2, const float* m2, const float* v2,
    const float* W4, const float* b4, const float* g4, const float* bt4, const float* m4, const float* v4,
    const float* qw)
{
    int t = threadIdx.x;  // 128 threads
    if (t < 128) {
        float a = g1[t] * rsqrtf(v1[t] + 1e-5f);
        for (int k = 0; k < 16; k++) d_W1f[t * 16 + k] = W1[t * 16 + k] * a;
        d_b1f[t] = (b1[t] - m1[t]) * a + bt1[t];
    }
    if (t < 64) {
        float a = g2[t] * rsqrtf(v2[t] + 1e-5f);
        float* w2 = (float*)d_W2f4;
        for (int k = 0; k < 128; k++) w2[t * 128 + k] = W2[t * 128 + k] * a;
        d_b2f[t] = (b2[t] - m2[t]) * a + bt2[t];
    }
    if (t < 32) {
        float a = g4[t] * rsqrtf(v4[t] + 1e-5f);
        for (int k = 0; k < 8; k++) d_W4f[t * 8 + k] = W4[t * 8 + k] * a;
        d_b4f[t] = (b4[t] - m4[t]) * a + bt4[t];
    }
    if (t < 24) {
        // combined G = Rz^T * Ry^T * Rx^T  (reference applies U^T per gate)
        float sx, cx, sy, cy, sz, cz;
        sincosf(0.5f * qw[t * 3 + 0], &sx, &cx);
        sincosf(0.5f * qw[t * 3 + 1], &sy, &cy);
        sincosf(0.5f * qw[t * 3 + 2], &sz, &cz);
        float cycx = cy * cx, sysx = sy * sx, sycx = sy * cx, cysx = cy * sx;
        float4 g;
        g.x = cz * cycx - sz * sysx;          // alpha.re
        g.y = -(cz * sysx + sz * cycx);       // alpha.im
        g.z = cz * sycx - sz * cysx;          // beta.re
        g.w = -(cz * cysx + sz * sycx);       // beta.im
        d_qg[t] = g;
    }
}

// ================= front MLP: x[B,16] -> angles[B,8] =================
#define FB 1024
#define FROWS 64        // rows per block
#define FTILE 16        // rows per iteration

__global__ void __launch_bounds__(128) front_kernel(const float* __restrict__ x,
                                                    const float* __restrict__ W3,
                                                    const float* __restrict__ b3)
{
    __shared__ float4 w2s4[64 * 32];      // 32 KB
    __shared__ float4 w3s4[8 * 16];       // 2 KB  natural [o][k4]
    __shared__ float4 xs4[FTILE][4];
    __shared__ float4 h1s4[FTILE][32];    // 8 KB
    __shared__ float4 h2s4[FTILE][16];    // 4 KB
    __shared__ float  b2s[64], b3s[8];

    int t = threadIdx.x;  // 128
    // stage weights
    for (int i = t; i < 64 * 32; i += 128) w2s4[i] = d_W2f4[i];
    {
        const float4* W34 = (const float4*)W3;
        if (t < 8 * 16) w3s4[t] = W34[t];
        if (t < 64) b2s[t] = d_b2f[t];
        if (t < 8)  b3s[t] = b3[t];
    }
    // W1 row for this thread's neuron in registers
    float w1[16];
    #pragma unroll
    for (int k = 0; k < 16; k++) w1[k] = d_W1f[t * 16 + k];
    float bb1 = d_b1f[t];
    __syncthreads();

    const float4* x4 = (const float4*)x;
    int base = blockIdx.x * FROWS;

    for (int it = 0; it < FROWS / FTILE; it++) {
        int rbase = base + it * FTILE;
        if (t < FTILE * 4) xs4[t >> 2][t & 3] = x4[(rbase + (t >> 2)) * 4 + (t & 3)];
        __syncthreads();

        // layer 1: thread = neuron, 16 rows
        #pragma unroll
        for (int r = 0; r < FTILE; r++) {
            float4 xa = xs4[r][0], xb = xs4[r][1], xc = xs4[r][2], xd = xs4[r][3];
            float a = bb1;
            a += w1[0]*xa.x + w1[1]*xa.y + w1[2]*xa.z + w1[3]*xa.w;
            a += w1[4]*xb.x + w1[5]*xb.y + w1[6]*xb.z + w1[7]*xb.w;
            a += w1[8]*xc.x + w1[9]*xc.y + w1[10]*xc.z + w1[11]*xc.w;
            a += w1[12]*xd.x + w1[13]*xd.y + w1[14]*xd.z + w1[15]*xd.w;
            ((float*)&h1s4[r][0])[t] = fmaxf(a, 0.f);
        }
        __syncthreads();

        // layer 2: o = t&63, rows half*8 .. half*8+7
        {
            int o = t & 63, half = t >> 6;
            float acc[8];
            #pragma unroll
            for (int rr = 0; rr < 8; rr++) acc[rr] = b2s[o];
            #pragma unroll 4
            for (int k4 = 0; k4 < 32; k4++) {
                float4 w = w2s4[o * 32 + k4];
                #pragma unroll
                for (int rr = 0; rr < 8; rr++) {
                    float4 h = h1s4[half * 8 + rr][k4];
                    acc[rr] += w.x*h.x + w.y*h.y + w.z*h.z + w.w*h.w;
                }
            }
            #pragma unroll
            for (int rr = 0; rr < 8; rr++)
                ((float*)&h2s4[half * 8 + rr][0])[o] = fmaxf(acc[rr], 0.f);
        }
        __syncthreads();

        // layer 3: r = t>>3 (16 rows), o = t&7, + tanh
        {
            int r = t >> 3, o = t & 7;
            float a = b3s[o];
            #pragma unroll
            for (int k4 = 0; k4 < 16; k4++) {
                float4 w = w3s4[o * 16 + k4];
                float4 h = h2s4[r][k4];
                a += w.x*h.x + w.y*h.y + w.z*h.z + w.w*h.w;
            }
            d_angles[(rbase + r) * 8 + o] = tanhf(a);
        }
        __syncthreads();
    }
}

// ================= quantum: generalized butterflies, no permutations =================
// amp index i[7:0]: bits 7..3 = lane bits 4..0 ; bits 2..0 = register slot.

// compile-time 8-bit parity as a type (true XOR-fold of all 8 bits)
template<int X> struct Par {
    static constexpr int val =
        ((X >> 7) ^ (X >> 6) ^ (X >> 5) ^ (X >> 4) ^ (X >> 3) ^ (X >> 2) ^ (X >> 1) ^ X) & 1;
};

template<int V, int R>
__device__ __forceinline__ void gate_vr(float2 st[8], float4 g, int lane)
{
    static_assert(Par<V & R>::val == 1, "pair/branch masks inconsistent");
    constexpr int vl = (V >> 3) & 31, vr = V & 7;
    constexpr int rl = (R >> 3) & 31, rr = R & 7;
    const float ar = g.x, bi = g.w;
    // fold lane-part of branch parity into the two sign-carrying coefficients
    bool lp = (__popc(lane & rl) & 1) != 0;
    float ai = lp ? -g.y : g.y;
    float br = lp ? -g.z : g.z;

    if constexpr (vl != 0 && vr == 0) {
        #pragma unroll
        for (int a = 0; a < 8; a++) {
            float pr = __shfl_xor_sync(FULLM, st[a].x, vl);
            float pi = __shfl_xor_sync(FULLM, st[a].y, vl);
            const bool sp = ((__popc(a & rr) & 1) != 0);
            float sai = sp ? -ai : ai;
            float sbr = sp ? -br : br;
            float nx = ar * st[a].x - sai * st[a].y + sbr * pr - bi * pi;
            float ny = ar * st[a].y + sai * st[a].x + sbr * pi + bi * pr;
            st[a].x = nx; st[a].y = ny;
        }
    } else if constexpr (vl != 0) {
        constexpr int hb = (vr & 4) ? 4 : ((vr & 2) ? 2 : 1);
        #pragma unroll
        for (int a = 0; a < 8; a++) {
            if (a & hb) continue;
            const int b = a ^ vr;
            float pax = __shfl_xor_sync(FULLM, st[b].x, vl);
            float pay = __shfl_xor_sync(FULLM, st[b].y, vl);
            float pbx = __shfl_xor_sync(FULLM, st[a].x, vl);
            float pby = __shfl_xor_sync(FULLM, st[a].y, vl);
            const bool spa = ((__popc(a & rr) & 1) != 0);
            const bool spb = ((__popc(b & rr) & 1) != 0);
            float saia = spa ? -ai : ai, sbra = spa ? -br : br;
            float saib = spb ? -ai : ai, sbrb = spb ? -br : br;
            float nax = ar * st[a].x - saia * st[a].y + sbra * pax - bi * pay;
            float nay = ar * st[a].y + saia * st[a].x + sbra * pay + bi * pax;
            float nbx = ar * st[b].x - saib * st[b].y + sbrb * pbx - bi * pby;
            float nby = ar * st[b].y + saib * st[b].x + sbrb * pby + bi * pbx;
            st[a].x = nax; st[a].y = nay; st[b].x = nbx; st[b].y = nby;
        }
    } else {   // purely local pairs
        constexpr int hb = (vr & 4) ? 4 : ((vr & 2) ? 2 : 1);
        #pragma unroll
        for (int a = 0; a < 8; a++) {
            if (a & hb) continue;
            const int b = a ^ vr;
            const bool spa = ((__popc(a & rr) & 1) != 0);
            const bool spb = ((__popc(b & rr) & 1) != 0);
            float saia = spa ? -ai : ai, sbra = spa ? -br : br;
            float saib = spb ? -ai : ai, sbrb = spb ? -br : br;
            float m0x = st[a].x, m0y = st[a].y, m1x = st[b].x, m1y = st[b].y;
            st[a].x = ar * m0x - saia * m0y + sbra * m1x - bi * m1y;
            st[a].y = ar * m0y + saia * m0x + sbra * m1y + bi * m1x;
            st[b].x = ar * m1x - saib * m1y + sbrb * m0x - bi * m0y;
            st[b].y = ar * m1y + saib * m1x + sbrb * m0y + bi * m0x;
        }
    }
}

template<int L, int Q>
__device__ __forceinline__ void gate(float2 st[8], const float4* gs, int lane)
{
    gate_vr<MK.v[L][Q], MK.r[L][Q]>(st, gs[L * 8 + Q], lane);
}

template<int M>
__device__ __forceinline__ float msel(const float p[8], int lane)
{
    float t = p[M & 7];
    return (__popc(lane & (M >> 3)) & 1) ? -t : t;
}

__global__ void __launch_bounds__(256) quantum_kernel()
{
    __shared__ float4 gs[24];
    int t = threadIdx.x;
    if (t < 24) gs[t] = d_qg[t];
    __syncthreads();

    int e = (blockIdx.x * blockDim.x + t) >> 5;
    int lane = t & 31;

    // ---- initial product state from RY(angles) applied to |0>; factor = (bit ? -sin : cos) ----
    float lamp = 1.f;
    #pragma unroll
    for (int q = 0; q < 5; q++) {
        float th = d_angles[e * 8 + q] * 0.5f;
        float sq, cq; __sincosf(th, &sq, &cq);
        lamp *= ((lane >> (4 - q)) & 1) ? -sq : cq;
    }
    float lc[3], ls[3];
    #pragma unroll
    for (int q = 5; q < 8; q++) {
        float th = d_angles[e * 8 + q] * 0.5f;
        __sincosf(th, &ls[q - 5], &lc[q - 5]);
    }
    float2 st[8];
    #pragma unroll
    for (int r = 0; r < 8; r++) {
        float v = lamp;
        v *= ((r >> 2) & 1) ? -ls[0] : lc[0];
        v *= ((r >> 1) & 1) ? -ls[1] : lc[1];
        v *= ( r       & 1) ? -ls[2] : lc[2];
        st[r].x = v; st[r].y = 0.f;
    }

    // ---- 3 layers x 8 combined SU(2) gates; CNOT ladders folded into masks ----
    gate<0,0>(st, gs, lane); gate<0,1>(st, gs, lane); gate<0,2>(st, gs, lane); gate<0,3>(st, gs, lane);
    gate<0,4>(st, gs, lane); gate<0,5>(st, gs, lane); gate<0,6>(st, gs, lane); gate<0,7>(st, gs, lane);
    gate<1,0>(st, gs, lane); gate<1,1>(st, gs, lane); gate<1,2>(st, gs, lane); gate<1,3>(st, gs, lane);
    gate<1,4>(st, gs, lane); gate<1,5>(st, gs, lane); gate<1,6>(st, gs, lane); gate<1,7>(st, gs, lane);
    gate<2,0>(st, gs, lane); gate<2,1>(st, gs, lane); gate<2,2>(st, gs, lane); gate<2,3>(st, gs, lane);
    gate<2,4>(st, gs, lane); gate<2,5>(st, gs, lane); gate<2,6>(st, gs, lane); gate<2,7>(st, gs, lane);

    // ---- probabilities, 3-bit WHT over register slots ----
    float p[8];
    #pragma unroll
    for (int r = 0; r < 8; r++) p[r] = st[r].x * st[r].x + st[r].y * st[r].y;
    #pragma unroll
    for (int s = 1; s < 8; s <<= 1) {
        #pragma unroll
        for (int a = 0; a < 8; a++) {
            if (a & s) continue;
            float u = p[a], v = p[a | s];
            p[a] = u + v; p[a | s] = u - v;
        }
    }
    // ---- signed lane values per qubit via final parity masks, then warp reduce ----
    float acc[8];
    acc[0] = msel<MK.rf[0]>(p, lane); acc[1] = msel<MK.rf[1]>(p, lane);
    acc[2] = msel<MK.rf[2]>(p, lane); acc[3] = msel<MK.rf[3]>(p, lane);
    acc[4] = msel<MK.rf[4]>(p, lane); acc[5] = msel<MK.rf[5]>(p, lane);
    acc[6] = msel<MK.rf[6]>(p, lane); acc[7] = msel<MK.rf[7]>(p, lane);
    #pragma unroll
    for (int off = 16; off; off >>= 1) {
        #pragma unroll
        for (int q = 0; q < 8; q++) acc[q] += __shfl_xor_sync(FULLM, acc[q], off);
    }
    if (lane == 0) {
        float4* o4 = (float4*)&d_qout[e * 8];
        o4[0] = make_float4(acc[0], acc[1], acc[2], acc[3]);
        o4[1] = make_float4(acc[4], acc[5], acc[6], acc[7]);
    }
}

// ================= tail MLP: qout[B,8] -> out[B,1] =================
__global__ void __launch_bounds__(256) tail_kernel(const float* __restrict__ W5, const float* __restrict__ b5,
                                                   const float* __restrict__ W6, const float* __restrict__ b6,
                                                   float* __restrict__ out)
{
    __shared__ float w4s[32 * 8], b4s[32], w5s[16 * 32], b5s[16], w6s[16], b6s;
    int t = threadIdx.x;  // 256
    w4s[t] = d_W4f[t];
    if (t < 32) b4s[t] = d_b4f[t];
    for (int i = t; i < 16 * 32; i += 256) w5s[i] = W5[i];
    if (t < 16) { b5s[t] = b5[t]; w6s[t] = W6[t]; }
    if (t == 0) b6s = b6[0];
    __syncthreads();

    int e = blockIdx.x * 256 + t;
    float4 qa = *(const float4*)&d_qout[e * 8];
    float4 qb = *(const float4*)&d_qout[e * 8 + 4];
    float q[8] = {qa.x, qa.y, qa.z, qa.w, qb.x, qb.y, qb.z, qb.w};

    float h5[16];
    #pragma unroll
    for (int j = 0; j < 16; j++) h5[j] = b5s[j];
    #pragma unroll
    for (int o = 0; o < 32; o++) {
        float a = b4s[o];
        #pragma unroll
        for (int k = 0; k < 8; k++) a += w4s[o * 8 + k] * q[k];
        a = fmaxf(a, 0.f);
        #pragma unroll
        for (int j = 0; j < 16; j++) h5[j] += w5s[j * 32 + o] * a;
    }
    float o6 = b6s;
    #pragma unroll
    for (int j = 0; j < 16; j++) o6 += fmaxf(h5[j], 0.f) * w6s[j];
    out[e] = o6;
}

// ================= launch =================
extern "C" void kernel_launch(void* const* d_in, const int* in_sizes, int n_in,
                              void* d_out, int out_size)
{
    const float* x   = (const float*)d_in[0];
    const float* W1  = (const float*)d_in[1];
    const float* b1  = (const float*)d_in[2];
    const float* g1  = (const float*)d_in[3];
    const float* bt1 = (const float*)d_in[4];
    const float* m1  = (const float*)d_in[5];
    const float* v1  = (const float*)d_in[6];
    const float* W2  = (const float*)d_in[7];
    const float* b2  = (const float*)d_in[8];
    const float* g2  = (const float*)d_in[9];
    const float* bt2 = (const float*)d_in[10];
    const float* m2  = (const float*)d_in[11];
    const float* v2  = (const float*)d_in[12];
    const float* W3  = (const float*)d_in[13];
    const float* b3  = (const float*)d_in[14];
    const float* qw  = (const float*)d_in[15];
    const float* W4  = (const float*)d_in[16];
    const float* b4  = (const float*)d_in[17];
    const float* g4  = (const float*)d_in[18];
    const float* bt4 = (const float*)d_in[19];
    const float* m4  = (const float*)d_in[20];
    const float* v4_ = (const float*)d_in[21];
    const float* W5  = (const float*)d_in[22];
    const float* b5  = (const float*)d_in[23];
    const float* W6  = (const float*)d_in[24];
    const float* b6  = (const float*)d_in[25];

    precompute_kernel<<<1, 128>>>(W1, b1, g1, bt1, m1, v1,
                                  W2, b2, g2, bt2, m2, v2,
                                  W4, b4, g4, bt4, m4, v4_, qw);
    front_kernel<<<FB, 128>>>(x, W3, b3);
    quantum_kernel<<<BATCH / 8, 256>>>();
    tail_kernel<<<BATCH / 256, 256>>>(W5, b5, W6, b6, (float*)d_out);
}

// round 8
// speedup vs baseline: 1.8611x; 1.1666x over previous
#include <cuda_runtime.h>
#include <math.h>

#define BATCH 65536
#define NQ 8
#define FULLM 0xffffffffu

typedef unsigned char u8;
typedef unsigned long long ull;

// ================= compile-time GF(2) algebra for CNOT ladder =================
struct M8 { u8 c[8]; };   // c[j] = column j bitmask (bit i set => M[i][j]=1)

__host__ __device__ constexpr u8 mv(const M8& m, u8 x) {
    u8 y = 0;
    for (int j = 0; j < 8; j++) if ((x >> j) & 1) y = (u8)(y ^ m.c[j]);
    return y;
}
__host__ __device__ constexpr M8 mm(const M8& a, const M8& b) {
    M8 r{}; for (int j = 0; j < 8; j++) r.c[j] = mv(a, b.c[j]); return r;
}
__host__ __device__ constexpr M8 ident() {
    M8 m{}; for (int j = 0; j < 8; j++) m.c[j] = (u8)(1u << j); return m;
}
__host__ __device__ constexpr M8 ladder() {
    M8 L = ident();
    for (int i = 0; i < 8; i++)
        for (int j = i + 1; j < 8; j++) {
            int cb = 7 - i, tb = 7 - j;
            M8 P = ident();
            P.c[cb] = (u8)((1u << cb) | (1u << tb));
            L = mm(L, P);
        }
    return L;
}
__host__ __device__ constexpr M8 minv(const M8& a) {
    u8 row[8] = {}, inv[8] = {};
    for (int i = 0; i < 8; i++) inv[i] = (u8)(1u << i);
    for (int i = 0; i < 8; i++)
        for (int j = 0; j < 8; j++)
            if ((a.c[j] >> i) & 1) row[i] = (u8)(row[i] | (1u << j));
    for (int col = 0; col < 8; col++) {
        int piv = col;
        while (!((row[piv] >> col) & 1)) piv++;
        u8 t = row[col]; row[col] = row[piv]; row[piv] = t;
        t = inv[col]; inv[col] = inv[piv]; inv[piv] = t;
        for (int i = 0; i < 8; i++)
            if (i != col && ((row[i] >> col) & 1)) { row[i] = (u8)(row[i] ^ row[col]); inv[i] = (u8)(inv[i] ^ inv[col]); }
    }
    M8 r{};
    for (int i = 0; i < 8; i++)
        for (int j = 0; j < 8; j++)
            if ((inv[i] >> j) & 1) r.c[j] = (u8)(r.c[j] | (1u << i));
    return r;
}
__host__ __device__ constexpr int par8(int x) { x ^= x >> 4; x ^= x >> 2; x ^= x >> 1; return x & 1; }

struct Masks {
    u8 v[3][8];
    u8 r[3][8];
    u8 rf[8];
};
__host__ __device__ constexpr Masks make_masks() {
    Masks mk{};
    M8 L = ladder();
    M8 C = ident();
    for (int l = 0; l < 3; l++) {
        M8 Ci = minv(C);
        for (int q = 0; q < 8; q++) {
            int B = 7 - q;
            mk.v[l][q] = mv(C, (u8)(1u << B));
            u8 rr = 0;
            for (int j = 0; j < 8; j++) if ((Ci.c[j] >> B) & 1) rr = (u8)(rr | (1u << j));
            mk.r[l][q] = rr;
        }
        C = mm(C, L);
    }
    M8 Cf = minv(C);
    for (int q = 0; q < 8; q++) {
        int B = 7 - q;
        u8 rr = 0;
        for (int j = 0; j < 8; j++) if ((Cf.c[j] >> B) & 1) rr = (u8)(rr | (1u << j));
        mk.rf[q] = rr;
    }
    return mk;
}
constexpr Masks MK = make_masks();

__host__ __device__ constexpr bool masks_ok() {
    constexpr Masks mk = make_masks();
    M8 L = ladder();
    M8 C = ident();
    for (int l = 0; l < 3; l++) {
        M8 Ci = minv(C);
        M8 P = mm(C, Ci);
        for (int j = 0; j < 8; j++) if (P.c[j] != (u8)(1u << j)) return false;
        for (int q = 0; q < 8; q++)
            if (par8(mk.v[l][q] & mk.r[l][q]) != 1) return false;
        C = mm(C, L);
    }
    return true;
}
static_assert(masks_ok(), "GF(2) mask algebra broken");

// ================= f32x2 helpers =================
__device__ __forceinline__ ull fpk(float lo, float hi) {
    ull r; asm("mov.b64 %0, {%1,%2};" : "=l"(r) : "f"(lo), "f"(hi)); return r;
}
__device__ __forceinline__ void funpk(ull v, float& lo, float& hi) {
    asm("mov.b64 {%0,%1}, %2;" : "=f"(lo), "=f"(hi) : "l"(v));
}
__device__ __forceinline__ ull mul2(ull a, ull b) {
    ull d; asm("mul.rn.f32x2 %0, %1, %2;" : "=l"(d) : "l"(a), "l"(b)); return d;
}
__device__ __forceinline__ ull fma2(ull a, ull b, ull c) {
    ull d; asm("fma.rn.f32x2 %0, %1, %2, %3;" : "=l"(d) : "l"(a), "l"(b), "l"(c)); return d;
}

// packed per-gate coefficients (exactly 8 ull = 64 bytes)
struct GatePack { ull AR, AIp, AIn, BRp, BRn, BIp, BIn, pad; };

// ================= device scratch =================
__device__ float    d_W1f[128 * 16];
__device__ float    d_b1f[128];
__device__ float4   d_W2f4[64 * 32];
__device__ float    d_b2f[64];
__device__ float    d_W4f[32 * 8];
__device__ float    d_b4f[32];
__device__ GatePack d_qgp[24];
__device__ float    d_angles[BATCH * NQ];
__device__ float    d_qout[BATCH * NQ];

// ================= precompute =================
__global__ void precompute_kernel(
    const float* W1, const float* b1, const float* g1, const float* bt1, const float* m1, const float* v1,
    const float* W2, const float* b2, const float* g2, const float* bt2, const float* m2, const float* v2,
    const float* W4, const float* b4, const float* g4, const float* bt4, const float* m4, const float* v4,
    const float* qw)
{
    int t = threadIdx.x;  // 128 threads
    if (t < 128) {
        float a = g1[t] * rsqrtf(v1[t] + 1e-5f);
        for (int k = 0; k < 16; k++) d_W1f[t * 16 + k] = W1[t * 16 + k] * a;
        d_b1f[t] = (b1[t] - m1[t]) * a + bt1[t];
    }
    if (t < 64) {
        float a = g2[t] * rsqrtf(v2[t] + 1e-5f);
        float* w2 = (float*)d_W2f4;
        for (int k = 0; k < 128; k++) w2[t * 128 + k] = W2[t * 128 + k] * a;
        d_b2f[t] = (b2[t] - m2[t]) * a + bt2[t];
    }
    if (t < 32) {
        float a = g4[t] * rsqrtf(v4[t] + 1e-5f);
        for (int k = 0; k < 8; k++) d_W4f[t * 8 + k] = W4[t * 8 + k] * a;
        d_b4f[t] = (b4[t] - m4[t]) * a + bt4[t];
    }
    if (t < 24) {
        // combined G = Rz^T * Ry^T * Rx^T  (reference applies U^T per gate)
        float sx, cx, sy, cy, sz, cz;
        sincosf(0.5f * qw[t * 3 + 0], &sx, &cx);
        sincosf(0.5f * qw[t * 3 + 1], &sy, &cy);
        sincosf(0.5f * qw[t * 3 + 2], &sz, &cz);
        float cycx = cy * cx, sysx = sy * sx, sycx = sy * cx, cysx = cy * sx;
        float ar  = cz * cycx - sz * sysx;        // alpha.re
        float ai0 = -(cz * sysx + sz * cycx);     // alpha.im
        float br0 = cz * sycx - sz * cysx;        // beta.re
        float bi  = -(cz * cysx + sz * sycx);     // beta.im
        Masks mk = make_masks();
        int l = t >> 3, q = t & 7;
        int rr = mk.r[l][q] & 7;
        float tau = (rr & 1) ? -1.f : 1.f;
        GatePack g;
        g.AR  = fpk(ar, ar);
        g.AIp = fpk(ai0,  tau * ai0);
        g.AIn = fpk(-ai0, -tau * ai0);
        g.BRp = fpk(br0,  tau * br0);
        g.BRn = fpk(-br0, -tau * br0);
        g.BIp = fpk(bi, bi);
        g.BIn = fpk(-bi, -bi);
        g.pad = 0;
        d_qgp[t] = g;
    }
}

// ================= front MLP: x[B,16] -> angles[B,8] =================
#define FB 1024
#define FROWS 64
#define FTILE 16

// w2 bank-swizzle: logical [o][k] stored at physical o*32 + (k ^ (o & 7)).
// Reading physical obase + (k4 ^ osw) therefore yields LOGICAL [o][k4],
// conflict-free across lanes; the matching h read uses logical k4 directly
// (warp-uniform address -> broadcast, free).
__global__ void __launch_bounds__(128) front_kernel(const float* __restrict__ x,
                                                    const float* __restrict__ W3,
                                                    const float* __restrict__ b3)
{
    __shared__ float4 w2s4[64 * 32];      // 32 KB, XOR-swizzled
    __shared__ float4 w3s4[8 * 16];       // 2 KB
    __shared__ float4 xs4[FTILE][4];
    __shared__ float4 h1s4[FTILE][32];    // 8 KB
    __shared__ float4 h2s4[FTILE][16];    // 4 KB
    __shared__ float  b2s[64], b3s[8];

    int t = threadIdx.x;  // 128
    for (int i = t; i < 64 * 32; i += 128) {
        int o = i >> 5, k = i & 31;
        w2s4[(o << 5) + (k ^ (o & 7))] = d_W2f4[i];
    }
    {
        const float4* W34 = (const float4*)W3;
        if (t < 8 * 16) w3s4[t] = W34[t];
        if (t < 64) b2s[t] = d_b2f[t];
        if (t < 8)  b3s[t] = b3[t];
    }
    float w1[16];
    #pragma unroll
    for (int k = 0; k < 16; k++) w1[k] = d_W1f[t * 16 + k];
    float bb1 = d_b1f[t];
    __syncthreads();

    const float4* x4 = (const float4*)x;
    int base = blockIdx.x * FROWS;

    for (int it = 0; it < FROWS / FTILE; it++) {
        int rbase = base + it * FTILE;
        if (t < FTILE * 4) xs4[t >> 2][t & 3] = x4[(rbase + (t >> 2)) * 4 + (t & 3)];
        __syncthreads();

        // layer 1: thread = neuron, 16 rows
        #pragma unroll
        for (int r = 0; r < FTILE; r++) {
            float4 xa = xs4[r][0], xb = xs4[r][1], xc = xs4[r][2], xd = xs4[r][3];
            float a = bb1;
            a += w1[0]*xa.x + w1[1]*xa.y + w1[2]*xa.z + w1[3]*xa.w;
            a += w1[4]*xb.x + w1[5]*xb.y + w1[6]*xb.z + w1[7]*xb.w;
            a += w1[8]*xc.x + w1[9]*xc.y + w1[10]*xc.z + w1[11]*xc.w;
            a += w1[12]*xd.x + w1[13]*xd.y + w1[14]*xd.z + w1[15]*xd.w;
            ((float*)&h1s4[r][0])[t] = fmaxf(a, 0.f);
        }
        __syncthreads();

        // layer 2: o = t&63, rows half*8 .. half*8+7
        {
            int o = t & 63, half = t >> 6;
            int obase = o << 5, osw = o & 7;
            float acc[8];
            #pragma unroll
            for (int rr = 0; rr < 8; rr++) acc[rr] = b2s[o];
            #pragma unroll 4
            for (int k4 = 0; k4 < 32; k4++) {
                float4 w = w2s4[obase + (k4 ^ osw)];   // logical [o][k4]
                #pragma unroll
                for (int rr = 0; rr < 8; rr++) {
                    float4 h = h1s4[half * 8 + rr][k4];  // logical k4 (broadcast)
                    acc[rr] += w.x*h.x + w.y*h.y + w.z*h.z + w.w*h.w;
                }
            }
            #pragma unroll
            for (int rr = 0; rr < 8; rr++)
                ((float*)&h2s4[half * 8 + rr][0])[o] = fmaxf(acc[rr], 0.f);
        }
        __syncthreads();

        // layer 3: r = t>>3 (16 rows), o = t&7, + tanh
        {
            int r = t >> 3, o = t & 7;
            float a = b3s[o];
            #pragma unroll
            for (int k4 = 0; k4 < 16; k4++) {
                float4 w = w3s4[o * 16 + k4];
                float4 h = h2s4[r][k4];
                a += w.x*h.x + w.y*h.y + w.z*h.z + w.w*h.w;
            }
            d_angles[(rbase + r) * 8 + o] = tanhf(a);
        }
        __syncthreads();
    }
}

// ================= quantum: f32x2 packed generalized butterflies =================
// amp index i[7:0]: bits 7..3 = lane bits 4..0 ; bits 2..0 = slot.
// Packed state: X[k] = (x_{2k}, x_{2k+1}), Y[k] = (y_{2k}, y_{2k+1}), k=0..3.

template<int X> struct Par {
    static constexpr int val =
        ((X >> 7) ^ (X >> 6) ^ (X >> 5) ^ (X >> 4) ^ (X >> 3) ^ (X >> 2) ^ (X >> 1) ^ X) & 1;
};

template<int V, int R>
__device__ __forceinline__ void gate2(ull X[4], ull Y[4], const GatePack* gp, int lane)
{
    static_assert(Par<V & R>::val == 1, "pair/branch masks inconsistent");
    constexpr int vl = (V >> 3) & 31, vr = V & 7;
    constexpr int rl = (R >> 3) & 31, rr = R & 7;

    ull AR  = gp->AR;
    ull BIp = gp->BIp;
    ull BIn = gp->BIn;
    // lane-parity sign fold: select between P/N packs (free when rl==0)
    bool lp = (__popc(lane & rl) & 1) != 0;
    ull AIpf = lp ? gp->AIn : gp->AIp;
    ull AInf = lp ? gp->AIp : gp->AIn;
    ull BRpf = lp ? gp->BRn : gp->BRp;
    ull BRnf = lp ? gp->BRp : gp->BRn;

    // partner packs (pre-gate values)
    ull PX[4], PY[4];
    #pragma unroll
    for (int k = 0; k < 4; k++) {
        const int kp = k ^ (vr >> 1);
        if constexpr ((vr & 1) != 0) {
            float xlo, xhi, ylo, yhi;
            funpk(X[kp], xlo, xhi);
            funpk(Y[kp], ylo, yhi);
            if constexpr (vl != 0) {
                xlo = __shfl_xor_sync(FULLM, xlo, vl);
                xhi = __shfl_xor_sync(FULLM, xhi, vl);
                ylo = __shfl_xor_sync(FULLM, ylo, vl);
                yhi = __shfl_xor_sync(FULLM, yhi, vl);
            }
            PX[k] = fpk(xhi, xlo);   // swapped halves
            PY[k] = fpk(yhi, ylo);
        } else {
            if constexpr (vl != 0) {
                PX[k] = __shfl_xor_sync(FULLM, X[kp], vl);
                PY[k] = __shfl_xor_sync(FULLM, Y[kp], vl);
            } else {
                PX[k] = X[kp];
                PY[k] = Y[kp];
            }
        }
    }
    // packed butterfly: per slot a
    //   nx = ar*x - s*ai*y + s*br*px - bi*py
    //   ny = ar*y + s*ai*x + s*br*py + bi*px,   s = (-1)^{par(a&rr)} * lambda
    #pragma unroll
    for (int k = 0; k < 4; k++) {
        const bool s0 = ((__popc((2 * k) & rr) & 1) != 0);
        ull AIx = s0 ? AIpf : AInf;   // coeff on Y in X-eq = -s*ai
        ull AIy = s0 ? AInf : AIpf;   // coeff on X in Y-eq = +s*ai
        ull BR  = s0 ? BRnf : BRpf;   // +s*br
        ull t1 = mul2(X[k], AR);
        t1 = fma2(Y[k],  AIx, t1);
        t1 = fma2(PX[k], BR,  t1);
        t1 = fma2(PY[k], BIn, t1);
        ull t2 = mul2(Y[k], AR);
        t2 = fma2(X[k],  AIy, t2);
        t2 = fma2(PY[k], BR,  t2);
        t2 = fma2(PX[k], BIp, t2);
        X[k] = t1; Y[k] = t2;
    }
}

template<int L, int Q>
__device__ __forceinline__ void gate(ull X[4], ull Y[4], const GatePack* gs, int lane)
{
    gate2<MK.v[L][Q], MK.r[L][Q]>(X, Y, gs + (L * 8 + Q), lane);
}

template<int M>
__device__ __forceinline__ float msel(const float p[8], int lane)
{
    float t = p[M & 7];
    return (__popc(lane & (M >> 3)) & 1) ? -t : t;
}

__global__ void __launch_bounds__(256) quantum_kernel()
{
    __shared__ GatePack gs[24];
    int t = threadIdx.x;
    if (t < 192) ((ull*)gs)[t] = ((const ull*)d_qgp)[t];
    __syncthreads();

    int e = (blockIdx.x * blockDim.x + t) >> 5;
    int lane = t & 31;

    // ---- initial product state from RY(angles) on |0>: factor (bit ? -sin : cos) ----
    float lamp = 1.f;
    #pragma unroll
    for (int q = 0; q < 5; q++) {
        float th = d_angles[e * 8 + q] * 0.5f;
        float sq, cq; __sincosf(th, &sq, &cq);
        lamp *= ((lane >> (4 - q)) & 1) ? -sq : cq;
    }
    float lc[3], ls[3];
    #pragma unroll
    for (int q = 5; q < 8; q++) {
        float th = d_angles[e * 8 + q] * 0.5f;
        __sincosf(th, &ls[q - 5], &lc[q - 5]);
    }
    ull X[4], Y[4];
    #pragma unroll
    for (int k = 0; k < 4; k++) {
        float v0 = lamp, v1 = lamp;
        int r0 = 2 * k, r1 = 2 * k + 1;
        v0 *= ((r0 >> 2) & 1) ? -ls[0] : lc[0];
        v0 *= ((r0 >> 1) & 1) ? -ls[1] : lc[1];
        v0 *= ( r0       & 1) ? -ls[2] : lc[2];
        v1 *= ((r1 >> 2) & 1) ? -ls[0] : lc[0];
        v1 *= ((r1 >> 1) & 1) ? -ls[1] : lc[1];
        v1 *= ( r1       & 1) ? -ls[2] : lc[2];
        X[k] = fpk(v0, v1);
        Y[k] = fpk(0.f, 0.f);
    }

    // ---- 3 layers x 8 packed SU(2) gates; CNOT ladders folded into masks ----
    gate<0,0>(X, Y, gs, lane); gate<0,1>(X, Y, gs, lane); gate<0,2>(X, Y, gs, lane); gate<0,3>(X, Y, gs, lane);
    gate<0,4>(X, Y, gs, lane); gate<0,5>(X, Y, gs, lane); gate<0,6>(X, Y, gs, lane); gate<0,7>(X, Y, gs, lane);
    gate<1,0>(X, Y, gs, lane); gate<1,1>(X, Y, gs, lane); gate<1,2>(X, Y, gs, lane); gate<1,3>(X, Y, gs, lane);
    gate<1,4>(X, Y, gs, lane); gate<1,5>(X, Y, gs, lane); gate<1,6>(X, Y, gs, lane); gate<1,7>(X, Y, gs, lane);
    gate<2,0>(X, Y, gs, lane); gate<2,1>(X, Y, gs, lane); gate<2,2>(X, Y, gs, lane); gate<2,3>(X, Y, gs, lane);
    gate<2,4>(X, Y, gs, lane); gate<2,5>(X, Y, gs, lane); gate<2,6>(X, Y, gs, lane); gate<2,7>(X, Y, gs, lane);

    // ---- probabilities ----
    float p[8];
    #pragma unroll
    for (int k = 0; k < 4; k++) {
        float xlo, xhi, ylo, yhi;
        funpk(X[k], xlo, xhi);
        funpk(Y[k], ylo, yhi);
        p[2 * k]     = xlo * xlo + ylo * ylo;
        p[2 * k + 1] = xhi * xhi + yhi * yhi;
    }
    // 3-bit WHT over slots
    #pragma unroll
    for (int s = 1; s < 8; s <<= 1) {
        #pragma unroll
        for (int a = 0; a < 8; a++) {
            if (a & s) continue;
            float u = p[a], v = p[a | s];
            p[a] = u + v; p[a | s] = u - v;
        }
    }
    float acc[8];
    acc[0] = msel<MK.rf[0]>(p, lane); acc[1] = msel<MK.rf[1]>(p, lane);
    acc[2] = msel<MK.rf[2]>(p, lane); acc[3] = msel<MK.rf[3]>(p, lane);
    acc[4] = msel<MK.rf[4]>(p, lane); acc[5] = msel<MK.rf[5]>(p, lane);
    acc[6] = msel<MK.rf[6]>(p, lane); acc[7] = msel<MK.rf[7]>(p, lane);
    #pragma unroll
    for (int off = 16; off; off >>= 1) {
        #pragma unroll
        for (int q = 0; q < 8; q++) acc[q] += __shfl_xor_sync(FULLM, acc[q], off);
    }
    if (lane == 0) {
        float4* o4 = (float4*)&d_qout[e * 8];
        o4[0] = make_float4(acc[0], acc[1], acc[2], acc[3]);
        o4[1] = make_float4(acc[4], acc[5], acc[6], acc[7]);
    }
}

// ================= tail MLP: qout[B,8] -> out[B,1] =================
__global__ void __launch_bounds__(256) tail_kernel(const float* __restrict__ W5, const float* __restrict__ b5,
                                                   const float* __restrict__ W6, const float* __restrict__ b6,
                                                   float* __restrict__ out)
{
    __shared__ float w4s[32 * 8], b4s[32], w5s[16 * 32], b5s[16], w6s[16], b6s;
    int t = threadIdx.x;  // 256
    w4s[t] = d_W4f[t];
    if (t < 32) b4s[t] = d_b4f[t];
    for (int i = t; i < 16 * 32; i += 256) w5s[i] = W5[i];
    if (t < 16) { b5s[t] = b5[t]; w6s[t] = W6[t]; }
    if (t == 0) b6s = b6[0];
    __syncthreads();

    int e = blockIdx.x * 256 + t;
    float4 qa = *(const float4*)&d_qout[e * 8];
    float4 qb = *(const float4*)&d_qout[e * 8 + 4];
    float q[8] = {qa.x, qa.y, qa.z, qa.w, qb.x, qb.y, qb.z, qb.w};

    float h5[16];
    #pragma unroll
    for (int j = 0; j < 16; j++) h5[j] = b5s[j];
    #pragma unroll
    for (int o = 0; o < 32; o++) {
        float a = b4s[o];
        #pragma unroll
        for (int k = 0; k < 8; k++) a += w4s[o * 8 + k] * q[k];
        a = fmaxf(a, 0.f);
        #pragma unroll
        for (int j = 0; j < 16; j++) h5[j] += w5s[j * 32 + o] * a;
    }
    float o6 = b6s;
    #pragma unroll
    for (int j = 0; j < 16; j++) o6 += fmaxf(h5[j], 0.f) * w6s[j];
    out[e] = o6;
}

// ================= launch =================
extern "C" void kernel_launch(void* const* d_in, const int* in_sizes, int n_in,
                              void* d_out, int out_size)
{
    const float* x   = (const float*)d_in[0];
    const float* W1  = (const float*)d_in[1];
    const float* b1  = (const float*)d_in[2];
    const float* g1  = (const float*)d_in[3];
    const float* bt1 = (const float*)d_in[4];
    const float* m1  = (const float*)d_in[5];
    const float* v1  = (const float*)d_in[6];
    const float* W2  = (const float*)d_in[7];
    const float* b2  = (const float*)d_in[8];
    const float* g2  = (const float*)d_in[9];
    const float* bt2 = (const float*)d_in[10];
    const float* m2  = (const float*)d_in[11];
    const float* v2  = (const float*)d_in[12];
    const float* W3  = (const float*)d_in[13];
    const float* b3  = (const float*)d_in[14];
    const float* qw  = (const float*)d_in[15];
    const float* W4  = (const float*)d_in[16];
    const float* b4  = (const float*)d_in[17];
    const float* g4  = (const float*)d_in[18];
    const float* bt4 = (const float*)d_in[19];
    const float* m4  = (const float*)d_in[20];
    const float* v4_ = (const float*)d_in[21];
    const float* W5  = (const float*)d_in[22];
    const float* b5  = (const float*)d_in[23];
    const float* W6  = (const float*)d_in[24];
    const float* b6  = (const float*)d_in[25];

    precompute_kernel<<<1, 128>>>(W1, b1, g1, bt1, m1, v1,
                                  W2, b2, g2, bt2, m2, v2,
                                  W4, b4, g4, bt4, m4, v4_, qw);
    front_kernel<<<FB, 128>>>(x, W3, b3);
    quantum_kernel<<<BATCH / 8, 256>>>();
    tail_kernel<<<BATCH / 256, 256>>>(W5, b5, W6, b6, (float*)d_out);
}